// round 14
// baseline (speedup 1.0000x reference)
#include <cuda_runtime.h>
#include <cuda_fp16.h>
#include <cuda_bf16.h>
#include <math.h>
#include <cstdint>

#define NWIN   1024
#define NT     64
#define DIMF   384
#define NHEADS 12
#define HDIM   32
#define MTOK   (NWIN * NT)          // 65536
#define QKVCOLS (3 * DIMF)          // 1152
#define MAX_LOGIT 4.605170185988091f // ln(100)

#define BK      32
#define ASTRIDE 40                   // 32 + 8 pad (80 bytes/row, 16B-multiple)

// ---------------------------------------------------------------------------
// Scratch (device globals)
// ---------------------------------------------------------------------------
__device__ float  g_qkv[(size_t)MTOK * QKVCOLS];   // 302 MB
__device__ float  g_bias[NHEADS * NT * NT];        // 16*sigmoid(rpb)
__device__ __half g_a[(size_t)MTOK * DIMF];        // 50 MB (fp16 acts, reused)
__device__ __half g_wq[(size_t)QKVCOLS * DIMF];    // [N][K] fp16
__device__ __half g_wp[(size_t)DIMF * DIMF];

// ---------------------------------------------------------------------------
__device__ __forceinline__ uint32_t smem_u32(const void* p) {
    uint32_t a;
    asm("{ .reg .u64 t; cvta.to.shared.u64 t, %1; cvt.u32.u64 %0, t; }" : "=r"(a) : "l"(p));
    return a;
}
__device__ __forceinline__ void cp_async16(uint32_t saddr, const void* gaddr) {
    asm volatile("cp.async.cg.shared.global [%0], [%1], 16;" :: "r"(saddr), "l"(gaddr) : "memory");
}
__device__ __forceinline__ void ldm_x4(uint32_t& r0, uint32_t& r1, uint32_t& r2, uint32_t& r3,
                                       uint32_t addr) {
    asm volatile("ldmatrix.sync.aligned.m8n8.x4.shared.b16 {%0,%1,%2,%3}, [%4];"
                 : "=r"(r0), "=r"(r1), "=r"(r2), "=r"(r3) : "r"(addr));
}
__device__ __forceinline__ void ldm_x4_trans(uint32_t& r0, uint32_t& r1, uint32_t& r2, uint32_t& r3,
                                             uint32_t addr) {
    asm volatile("ldmatrix.sync.aligned.m8n8.x4.trans.shared.b16 {%0,%1,%2,%3}, [%4];"
                 : "=r"(r0), "=r"(r1), "=r"(r2), "=r"(r3) : "r"(addr));
}
__device__ __forceinline__ void mma16816(float& c0, float& c1, float& c2, float& c3,
                                         uint32_t a0, uint32_t a1, uint32_t a2, uint32_t a3,
                                         uint32_t b0, uint32_t b1) {
    asm volatile("mma.sync.aligned.m16n8k16.row.col.f32.f16.f16.f32 "
                 "{%0,%1,%2,%3}, {%4,%5,%6,%7}, {%8,%9}, {%0,%1,%2,%3};"
                 : "+f"(c0), "+f"(c1), "+f"(c2), "+f"(c3)
                 : "r"(a0), "r"(a1), "r"(a2), "r"(a3), "r"(b0), "r"(b1));
}
__device__ __forceinline__ void mma16816bf(float* c,
                                           const uint32_t* a,
                                           uint32_t b0, uint32_t b1) {
    asm volatile("mma.sync.aligned.m16n8k16.row.col.f32.bf16.bf16.f32 "
                 "{%0,%1,%2,%3}, {%4,%5,%6,%7}, {%8,%9}, {%0,%1,%2,%3};"
                 : "+f"(c[0]), "+f"(c[1]), "+f"(c[2]), "+f"(c[3])
                 : "r"(a[0]), "r"(a[1]), "r"(a[2]), "r"(a[3]), "r"(b0), "r"(b1));
}
// split float pair into packed bf16 hi and lo words
__device__ __forceinline__ void splitpack(float x, float y, uint32_t& hi, uint32_t& lo) {
    __nv_bfloat16 hx = __float2bfloat16(x), hy = __float2bfloat16(y);
    __nv_bfloat162 h2; h2.x = hx; h2.y = hy;
    hi = *(uint32_t*)&h2;
    __nv_bfloat16 lx = __float2bfloat16(x - __bfloat162float(hx));
    __nv_bfloat16 ly = __float2bfloat16(y - __bfloat162float(hy));
    __nv_bfloat162 l2; l2.x = lx; l2.y = ly;
    lo = *(uint32_t*)&l2;
}

// ---------------------------------------------------------------------------
// K0: continuous position bias MLP + gather + 16*sigmoid
// ---------------------------------------------------------------------------
__global__ void rpb_kernel(const float* __restrict__ table,
                           const float* __restrict__ w1,
                           const float* __restrict__ b1,
                           const float* __restrict__ w2,
                           const float* __restrict__ b2,
                           const int*   __restrict__ idx)
{
    __shared__ float s_w1[1024];
    __shared__ float s_b1[512];
    __shared__ float s_w2[512 * 12];
    __shared__ float s_b2[12];
    __shared__ float s_rpb[225 * 12];
    int tid = threadIdx.x;

    for (int i = tid; i < 1024; i += 256) s_w1[i] = w1[i];
    for (int i = tid; i < 512;  i += 256) s_b1[i] = b1[i];
    for (int i = tid; i < 6144; i += 256) s_w2[i] = w2[i];
    if (tid < 12) s_b2[tid] = b2[tid];
    __syncthreads();

    if (tid < 225) {
        float t0 = table[tid * 2 + 0];
        float t1 = table[tid * 2 + 1];
        float acc[12];
        #pragma unroll
        for (int h = 0; h < 12; h++) acc[h] = s_b2[h];
        for (int j = 0; j < 512; j++) {
            float hj = fmaf(t0, s_w1[j], fmaf(t1, s_w1[512 + j], s_b1[j]));
            hj = fmaxf(hj, 0.0f);
            #pragma unroll
            for (int h = 0; h < 12; h++)
                acc[h] = fmaf(hj, s_w2[j * 12 + h], acc[h]);
        }
        #pragma unroll
        for (int h = 0; h < 12; h++) s_rpb[tid * 12 + h] = acc[h];
    }
    __syncthreads();

    for (int o = tid; o < NHEADS * NT * NT; o += 256) {
        int h = o >> 12;
        int p = o & 4095;
        float r = s_rpb[idx[p] * 12 + h];
        g_bias[o] = 16.0f / (1.0f + expf(-r));
    }
}

// ---------------------------------------------------------------------------
// Convert fp32 activations -> fp16
// ---------------------------------------------------------------------------
__global__ __launch_bounds__(256) void conv_act(const float* __restrict__ in,
                                                __half* __restrict__ out)
{
    size_t t = (size_t)blockIdx.x * 256 + threadIdx.x;
    if (t >= (size_t)MTOK * 96) return;
    float4 v = *(const float4*)(in + t * 4);
    __half2 p0 = __floats2half2_rn(v.x, v.y);
    __half2 p1 = __floats2half2_rn(v.z, v.w);
    __half2* o = (__half2*)(out + t * 4);
    o[0] = p0; o[1] = p1;
}

// Convert + transpose weights [384 x Ncols] fp32 -> fp16 [Ncols x 384]
__global__ __launch_bounds__(256) void conv_w(const float* __restrict__ w,
                                              __half* __restrict__ out, int Ncols)
{
    int t = blockIdx.x * 256 + threadIdx.x;
    if (t >= DIMF * Ncols) return;
    int k = t / Ncols, n = t % Ncols;
    out[(size_t)n * DIMF + k] = __float2half(w[(size_t)k * Ncols + n]);
}

// ---------------------------------------------------------------------------
// HMMA fp16 GEMM (R5-proven config): C[M,N] = A[M,K] @ B[N,K]^T (+bias)
// ---------------------------------------------------------------------------
__global__ __launch_bounds__(256) void gemm_hmma(
    const __half* __restrict__ A, const __half* __restrict__ B,
    const float* __restrict__ bias, float* __restrict__ C, int N, int K)
{
    __shared__ alignas(16) __half sA[2][128 * ASTRIDE];
    __shared__ alignas(16) __half sB[2][128 * ASTRIDE];

    const int tid  = threadIdx.x;
    const int wid  = tid >> 5, lane = tid & 31;
    const int m0   = blockIdx.y * 128, n0 = blockIdx.x * 128;
    const int wm   = (wid & 1) * 64;
    const int wn   = (wid >> 1) * 32;
    const int KT   = K / BK;

    float c[4][4][4];
    #pragma unroll
    for (int i = 0; i < 4; i++)
        #pragma unroll
        for (int j = 0; j < 4; j++)
            #pragma unroll
            for (int l = 0; l < 4; l++) c[i][j][l] = 0.0f;

    const int lrow = tid >> 2;
    const int lq   = tid & 3;
    const __half* gA0 = A + (size_t)(m0 + lrow)      * K + lq * 8;
    const __half* gA1 = A + (size_t)(m0 + lrow + 64) * K + lq * 8;
    const __half* gB0 = B + (size_t)(n0 + lrow)      * K + lq * 8;
    const __half* gB1 = B + (size_t)(n0 + lrow + 64) * K + lq * 8;

    uint32_t sA_st[2], sB_st[2], sA_base[2], sB_base[2];
    #pragma unroll
    for (int s = 0; s < 2; s++) {
        sA_base[s] = smem_u32(&sA[s][0]);
        sB_base[s] = smem_u32(&sB[s][0]);
        sA_st[s] = sA_base[s] + (lrow * ASTRIDE + lq * 8) * 2;
        sB_st[s] = sB_base[s] + (lrow * ASTRIDE + lq * 8) * 2;
    }
    const uint32_t rowoff = 64 * ASTRIDE * 2;

    const uint32_t a_off = ((wm + (lane & 15)) * ASTRIDE + (lane >> 4) * 8) * 2;
    const uint32_t b_off = ((wn + (lane & 7) + ((lane >> 4) << 3)) * ASTRIDE
                            + ((lane >> 3) & 1) * 8) * 2;

    {
        cp_async16(sA_st[0],          gA0);
        cp_async16(sA_st[0] + rowoff, gA1);
        cp_async16(sB_st[0],          gB0);
        cp_async16(sB_st[0] + rowoff, gB1);
        asm volatile("cp.async.commit_group;" ::: "memory");
    }

    for (int kt = 0; kt < KT; kt++) {
        const int cur = kt & 1;
        if (kt + 1 < KT) {
            const int nxt = cur ^ 1;
            const size_t ko = (size_t)(kt + 1) * BK;
            cp_async16(sA_st[nxt],          gA0 + ko);
            cp_async16(sA_st[nxt] + rowoff, gA1 + ko);
            cp_async16(sB_st[nxt],          gB0 + ko);
            cp_async16(sB_st[nxt] + rowoff, gB1 + ko);
            asm volatile("cp.async.commit_group;" ::: "memory");
            asm volatile("cp.async.wait_group 1;" ::: "memory");
        } else {
            asm volatile("cp.async.wait_group 0;" ::: "memory");
        }
        __syncthreads();

        const uint32_t aS = sA_base[cur] + a_off;
        const uint32_t bS = sB_base[cur] + b_off;
        #pragma unroll
        for (int kk = 0; kk < 2; kk++) {
            uint32_t a[4][4];
            #pragma unroll
            for (int mi = 0; mi < 4; mi++)
                ldm_x4(a[mi][0], a[mi][1], a[mi][2], a[mi][3],
                       aS + (mi * 16 * ASTRIDE + kk * 16) * 2);
            uint32_t b[4][2];
            #pragma unroll
            for (int p = 0; p < 2; p++) {
                uint32_t r0, r1, r2, r3;
                ldm_x4(r0, r1, r2, r3, bS + (p * 16 * ASTRIDE + kk * 16) * 2);
                b[p * 2 + 0][0] = r0; b[p * 2 + 0][1] = r1;
                b[p * 2 + 1][0] = r2; b[p * 2 + 1][1] = r3;
            }
            #pragma unroll
            for (int mi = 0; mi < 4; mi++)
                #pragma unroll
                for (int ni = 0; ni < 4; ni++)
                    mma16816(c[mi][ni][0], c[mi][ni][1], c[mi][ni][2], c[mi][ni][3],
                             a[mi][0], a[mi][1], a[mi][2], a[mi][3],
                             b[ni][0], b[ni][1]);
        }
        __syncthreads();
    }

    const int g = lane >> 2, tg = lane & 3;
    #pragma unroll
    for (int ni = 0; ni < 4; ni++) {
        const int col = n0 + wn + ni * 8 + tg * 2;
        float b0 = 0.0f, b1 = 0.0f;
        if (bias) { b0 = bias[col]; b1 = bias[col + 1]; }
        #pragma unroll
        for (int mi = 0; mi < 4; mi++) {
            const int row = m0 + wm + mi * 16 + g;
            float2 v0 = make_float2(c[mi][ni][0] + b0, c[mi][ni][1] + b1);
            float2 v1 = make_float2(c[mi][ni][2] + b0, c[mi][ni][3] + b1);
            *(float2*)(C + (size_t)row * N + col)       = v0;
            *(float2*)(C + (size_t)(row + 8) * N + col) = v1;
        }
    }
}

// ---------------------------------------------------------------------------
// K2: attention via split-2 bf16 tensor-core MMA. One CTA per (head, window).
// V kept in natural [key][d] layout; PV B-operand via ldmatrix.x4.trans.
// ---------------------------------------------------------------------------
__global__ __launch_bounds__(128) void attn_kernel(
    const float* __restrict__ mask, const float* __restrict__ lscale)
{
    const int h   = blockIdx.x;
    const int b   = blockIdx.y;
    const int tid = threadIdx.x;
    const int wid = tid >> 5, lane = tid & 31;
    const int g   = lane >> 2, tg = lane & 3;
    const int wm  = wid * 16;

    __shared__ alignas(16) __nv_bfloat16 sqh[64 * ASTRIDE], sql[64 * ASTRIDE];
    __shared__ alignas(16) __nv_bfloat16 skh[64 * ASTRIDE], skl[64 * ASTRIDE];
    __shared__ alignas(16) __nv_bfloat16 svh[64 * ASTRIDE], svl[64 * ASTRIDE]; // [key][d]

    const float* qkv = g_qkv + (size_t)b * 64 * QKVCOLS + h * 32;

    // ---- load + normalize q (threads 0-63) / k (threads 64-127), split bf16
    {
        int r = tid & 63;
        const float4* p = (const float4*)(qkv + (size_t)r * QKVCOLS + (tid < 64 ? 0 : 384));
        float v[32];
        #pragma unroll
        for (int i = 0; i < 8; i++) {
            float4 t = p[i];
            v[i * 4 + 0] = t.x; v[i * 4 + 1] = t.y; v[i * 4 + 2] = t.z; v[i * 4 + 3] = t.w;
        }
        float ss = 0.0f;
        #pragma unroll
        for (int i = 0; i < 32; i++) ss = fmaf(v[i], v[i], ss);
        float sc = rsqrtf(fmaxf(ss, 1e-12f));
        if (tid < 64) sc *= __expf(fminf(lscale[h], MAX_LOGIT));
        uint32_t* rh = (uint32_t*)((tid < 64 ? sqh : skh) + r * ASTRIDE);
        uint32_t* rl = (uint32_t*)((tid < 64 ? sql : skl) + r * ASTRIDE);
        #pragma unroll
        for (int i = 0; i < 16; i++) {
            uint32_t hi, lo;
            splitpack(v[2 * i] * sc, v[2 * i + 1] * sc, hi, lo);
            rh[i] = hi; rl[i] = lo;
        }
    }
    // ---- load v (all threads), split bf16, natural [key][d] layout, vectorized
    {
        int r = tid >> 1, dh = (tid & 1) * 16;
        const float4* p = (const float4*)(qkv + 768 + (size_t)r * QKVCOLS + dh);
        uint32_t wh[8], wl[8];
        #pragma unroll
        for (int i = 0; i < 4; i++) {
            float4 t = p[i];
            splitpack(t.x, t.y, wh[i * 2 + 0], wl[i * 2 + 0]);
            splitpack(t.z, t.w, wh[i * 2 + 1], wl[i * 2 + 1]);
        }
        uint4* oh = (uint4*)(svh + r * ASTRIDE + dh);
        uint4* ol = (uint4*)(svl + r * ASTRIDE + dh);
        oh[0] = make_uint4(wh[0], wh[1], wh[2], wh[3]);
        oh[1] = make_uint4(wh[4], wh[5], wh[6], wh[7]);
        ol[0] = make_uint4(wl[0], wl[1], wl[2], wl[3]);
        ol[1] = make_uint4(wl[4], wl[5], wl[6], wl[7]);
    }
    __syncthreads();

    // ---- scores: c[8 key-frags][4], split-2 bf16 MMA
    float c[8][4];
    #pragma unroll
    for (int j = 0; j < 8; j++)
        #pragma unroll
        for (int l = 0; l < 4; l++) c[j][l] = 0.0f;

    const uint32_t a_off = ((wm + (lane & 15)) * ASTRIDE + (lane >> 4) * 8) * 2;
    const uint32_t b_off = (((lane & 7) + ((lane >> 4) << 3)) * ASTRIDE
                            + ((lane >> 3) & 1) * 8) * 2;

    uint32_t ah[2][4], al[2][4];
    ldm_x4(ah[0][0], ah[0][1], ah[0][2], ah[0][3], smem_u32(sqh) + a_off);
    ldm_x4(ah[1][0], ah[1][1], ah[1][2], ah[1][3], smem_u32(sqh) + a_off + 32);
    ldm_x4(al[0][0], al[0][1], al[0][2], al[0][3], smem_u32(sql) + a_off);
    ldm_x4(al[1][0], al[1][1], al[1][2], al[1][3], smem_u32(sql) + a_off + 32);

    #pragma unroll
    for (int kb = 0; kb < 4; kb++) {
        uint32_t bh[2][2][2], bl[2][2][2];   // [kk][nfrag][2]
        #pragma unroll
        for (int kk = 0; kk < 2; kk++) {
            uint32_t r0, r1, r2, r3;
            ldm_x4(r0, r1, r2, r3,
                   smem_u32(skh) + b_off + kb * (16 * ASTRIDE * 2) + kk * 32);
            bh[kk][0][0] = r0; bh[kk][0][1] = r1; bh[kk][1][0] = r2; bh[kk][1][1] = r3;
            ldm_x4(r0, r1, r2, r3,
                   smem_u32(skl) + b_off + kb * (16 * ASTRIDE * 2) + kk * 32);
            bl[kk][0][0] = r0; bl[kk][0][1] = r1; bl[kk][1][0] = r2; bl[kk][1][1] = r3;
        }
        #pragma unroll
        for (int nf = 0; nf < 2; nf++) {
            int n = kb * 2 + nf;
            #pragma unroll
            for (int kk = 0; kk < 2; kk++) {
                mma16816bf(c[n], ah[kk], bh[kk][nf][0], bh[kk][nf][1]);  // hi*hi
                mma16816bf(c[n], ah[kk], bl[kk][nf][0], bl[kk][nf][1]);  // hi*lo
                mma16816bf(c[n], al[kk], bh[kk][nf][0], bh[kk][nf][1]);  // lo*hi
            }
        }
    }

    // ---- add bias (per head) + mask (per window group)
    {
        const float* bi = g_bias + (size_t)h * 4096;
        const float* mk = mask + (size_t)(b & 63) * 4096;
        #pragma unroll
        for (int j = 0; j < 8; j++) {
            int cb = j * 8 + tg * 2;
            int r0i = (wm + g) * 64 + cb, r1i = (wm + g + 8) * 64 + cb;
            float2 b0 = *(const float2*)(bi + r0i);
            float2 b1 = *(const float2*)(bi + r1i);
            float2 m0 = *(const float2*)(mk + r0i);
            float2 m1 = *(const float2*)(mk + r1i);
            c[j][0] += b0.x + m0.x; c[j][1] += b0.y + m0.y;
            c[j][2] += b1.x + m1.x; c[j][3] += b1.y + m1.y;
        }
    }

    // ---- fragment softmax (rows wm+g and wm+g+8)
    {
        float m0 = -1e30f, m1 = -1e30f;
        #pragma unroll
        for (int j = 0; j < 8; j++) {
            m0 = fmaxf(m0, fmaxf(c[j][0], c[j][1]));
            m1 = fmaxf(m1, fmaxf(c[j][2], c[j][3]));
        }
        m0 = fmaxf(m0, __shfl_xor_sync(0xFFFFFFFF, m0, 1));
        m0 = fmaxf(m0, __shfl_xor_sync(0xFFFFFFFF, m0, 2));
        m1 = fmaxf(m1, __shfl_xor_sync(0xFFFFFFFF, m1, 1));
        m1 = fmaxf(m1, __shfl_xor_sync(0xFFFFFFFF, m1, 2));
        float s0 = 0.0f, s1 = 0.0f;
        #pragma unroll
        for (int j = 0; j < 8; j++) {
            c[j][0] = __expf(c[j][0] - m0); s0 += c[j][0];
            c[j][1] = __expf(c[j][1] - m0); s0 += c[j][1];
            c[j][2] = __expf(c[j][2] - m1); s1 += c[j][2];
            c[j][3] = __expf(c[j][3] - m1); s1 += c[j][3];
        }
        s0 += __shfl_xor_sync(0xFFFFFFFF, s0, 1);
        s0 += __shfl_xor_sync(0xFFFFFFFF, s0, 2);
        s1 += __shfl_xor_sync(0xFFFFFFFF, s1, 1);
        s1 += __shfl_xor_sync(0xFFFFFFFF, s1, 2);
        float i0 = 1.0f / s0, i1 = 1.0f / s1;
        #pragma unroll
        for (int j = 0; j < 8; j++) {
            c[j][0] *= i0; c[j][1] *= i0; c[j][2] *= i1; c[j][3] *= i1;
        }
    }

    // ---- pack P fragments (A-layout) with split-2
    uint32_t ph[4][4], pl[4][4];   // [kstep][4 regs]
    #pragma unroll
    for (int ks = 0; ks < 4; ks++) {
        int j0 = 2 * ks, j1 = 2 * ks + 1;
        splitpack(c[j0][0], c[j0][1], ph[ks][0], pl[ks][0]);
        splitpack(c[j0][2], c[j0][3], ph[ks][1], pl[ks][1]);
        splitpack(c[j1][0], c[j1][1], ph[ks][2], pl[ks][2]);
        splitpack(c[j1][2], c[j1][3], ph[ks][3], pl[ks][3]);
    }

    // ---- PV: o[4 d-frags][4]; B via trans-ldmatrix of natural-layout V
    float o[4][4];
    #pragma unroll
    for (int n = 0; n < 4; n++)
        #pragma unroll
        for (int l = 0; l < 4; l++) o[n][l] = 0.0f;

    // trans B addressing: row = key (lane&7) + ((lane>>3)&1)*8, col = d (lane>>4)*8
    const uint32_t vt_off = (((lane & 7) + ((lane >> 3) & 1) * 8) * ASTRIDE
                             + (lane >> 4) * 8) * 2;
    #pragma unroll
    for (int ng = 0; ng < 2; ng++) {          // d 16-col group
        #pragma unroll
        for (int ks = 0; ks < 4; ks++) {      // key 16-row block
            uint32_t r0, r1, r2, r3, s0, s1, s2, s3;
            ldm_x4_trans(r0, r1, r2, r3,
                         smem_u32(svh) + vt_off + ks * (16 * ASTRIDE * 2) + ng * 32);
            ldm_x4_trans(s0, s1, s2, s3,
                         smem_u32(svl) + vt_off + ks * (16 * ASTRIDE * 2) + ng * 32);
            int n0i = ng * 2, n1i = ng * 2 + 1;
            mma16816bf(o[n0i], ph[ks], r0, r1);   // ph*vh
            mma16816bf(o[n0i], ph[ks], s0, s1);   // ph*vl
            mma16816bf(o[n0i], pl[ks], r0, r1);   // pl*vh
            mma16816bf(o[n1i], ph[ks], r2, r3);
            mma16816bf(o[n1i], ph[ks], s2, s3);
            mma16816bf(o[n1i], pl[ks], r2, r3);
        }
    }

    // ---- write fp16 ctx to g_a
    {
        __half* o0 = g_a + (size_t)(b * 64 + wm + g) * DIMF + h * 32;
        __half* o1 = o0 + (size_t)8 * DIMF;
        #pragma unroll
        for (int n = 0; n < 4; n++) {
            int col = n * 8 + tg * 2;
            *(__half2*)(o0 + col) = __floats2half2_rn(o[n][0], o[n][1]);
            *(__half2*)(o1 + col) = __floats2half2_rn(o[n][2], o[n][3]);
        }
    }
}

// ---------------------------------------------------------------------------
extern "C" void kernel_launch(void* const* d_in, const int* in_sizes, int n_in,
                              void* d_out, int out_size)
{
    const float* x           = (const float*)d_in[0];
    const float* mask        = (const float*)d_in[1];
    const float* qkv_w       = (const float*)d_in[2];
    const float* proj_w      = (const float*)d_in[3];
    const float* proj_b      = (const float*)d_in[4];
    const float* cpb_w1      = (const float*)d_in[5];
    const float* cpb_b1      = (const float*)d_in[6];
    const float* cpb_w2      = (const float*)d_in[7];
    const float* cpb_b2      = (const float*)d_in[8];
    const float* logit_scale = (const float*)d_in[9];
    const float* rpb_table   = (const float*)d_in[10];
    const int*   rpb_idx     = (const int*)d_in[11];
    float* out = (float*)d_out;

    float* qkv_ptr = nullptr;
    __half *a_ptr = nullptr, *wq_ptr = nullptr, *wp_ptr = nullptr;
    cudaGetSymbolAddress((void**)&qkv_ptr, g_qkv);
    cudaGetSymbolAddress((void**)&a_ptr,  g_a);
    cudaGetSymbolAddress((void**)&wq_ptr, g_wq);
    cudaGetSymbolAddress((void**)&wp_ptr, g_wp);

    // K0: CPB bias table + weight converts (tiny)
    rpb_kernel<<<1, 256>>>(rpb_table, cpb_w1, cpb_b1, cpb_w2, cpb_b2, rpb_idx);
    conv_w<<<(DIMF * QKVCOLS + 255) / 256, 256>>>(qkv_w, wq_ptr, QKVCOLS);
    conv_w<<<(DIMF * DIMF + 255) / 256, 256>>>(proj_w, wp_ptr, DIMF);

    // convert activations for QKV GEMM
    conv_act<<<(int)(((size_t)MTOK * 96 + 255) / 256), 256>>>(x, a_ptr);

    // K1: QKV GEMM (65536 x 1152 x 384), fp16 HMMA
    gemm_hmma<<<dim3(QKVCOLS / 128, MTOK / 128), 256>>>(
        a_ptr, wq_ptr, nullptr, qkv_ptr, QKVCOLS, DIMF);

    // K2: attention per (head, window); tensor-core split-bf16; writes fp16 ctx
    attn_kernel<<<dim3(NHEADS, NWIN), 128>>>(mask, logit_scale);

    // K3: projection (65536 x 384 x 384) + bias, fp16 HMMA
    gemm_hmma<<<dim3(DIMF / 128, MTOK / 128), 256>>>(
        a_ptr, wp_ptr, proj_b, out, DIMF, DIMF);
}

// round 17
// speedup vs baseline: 1.0315x; 1.0315x over previous
#include <cuda_runtime.h>
#include <cuda_fp16.h>
#include <cuda_bf16.h>
#include <math.h>
#include <cstdint>

#define NWIN   1024
#define NT     64
#define DIMF   384
#define NHEADS 12
#define HDIM   32
#define MTOK   (NWIN * NT)          // 65536
#define QKVCOLS (3 * DIMF)          // 1152
#define QKCOLS  (2 * DIMF)          // 768 (q,k only; v stored fp16 separately)
#define MAX_LOGIT 4.605170185988091f // ln(100)

#define BK      32
#define ASTRIDE 40                   // 32 + 8 pad (80 bytes/row, 16B-multiple)

// ---------------------------------------------------------------------------
// Scratch (device globals)
// ---------------------------------------------------------------------------
__device__ float  g_qkv[(size_t)MTOK * QKCOLS];    // 201 MB (q,k fp32, stride 768)
__device__ __half g_v[(size_t)MTOK * DIMF];        // 50 MB  (v fp16, stride 384)
__device__ float  g_bias[NHEADS * NT * NT];        // 16*sigmoid(rpb)
__device__ float  g_bm[(size_t)NHEADS * 64 * NT * NT]; // bias+mask combined, 12.6 MB
__device__ __half g_a[(size_t)MTOK * DIMF];        // 50 MB (fp16 acts, reused for ctx)
__device__ __half g_wq[(size_t)QKVCOLS * DIMF];    // [N][K] fp16
__device__ __half g_wp[(size_t)DIMF * DIMF];

// ---------------------------------------------------------------------------
__device__ __forceinline__ uint32_t smem_u32(const void* p) {
    uint32_t a;
    asm("{ .reg .u64 t; cvta.to.shared.u64 t, %1; cvt.u32.u64 %0, t; }" : "=r"(a) : "l"(p));
    return a;
}
__device__ __forceinline__ void cp_async16(uint32_t saddr, const void* gaddr) {
    asm volatile("cp.async.cg.shared.global [%0], [%1], 16;" :: "r"(saddr), "l"(gaddr) : "memory");
}
__device__ __forceinline__ void ldm_x4(uint32_t& r0, uint32_t& r1, uint32_t& r2, uint32_t& r3,
                                       uint32_t addr) {
    asm volatile("ldmatrix.sync.aligned.m8n8.x4.shared.b16 {%0,%1,%2,%3}, [%4];"
                 : "=r"(r0), "=r"(r1), "=r"(r2), "=r"(r3) : "r"(addr));
}
__device__ __forceinline__ void ldm_x4_trans(uint32_t& r0, uint32_t& r1, uint32_t& r2, uint32_t& r3,
                                             uint32_t addr) {
    asm volatile("ldmatrix.sync.aligned.m8n8.x4.trans.shared.b16 {%0,%1,%2,%3}, [%4];"
                 : "=r"(r0), "=r"(r1), "=r"(r2), "=r"(r3) : "r"(addr));
}
__device__ __forceinline__ void mma16816(float& c0, float& c1, float& c2, float& c3,
                                         uint32_t a0, uint32_t a1, uint32_t a2, uint32_t a3,
                                         uint32_t b0, uint32_t b1) {
    asm volatile("mma.sync.aligned.m16n8k16.row.col.f32.f16.f16.f32 "
                 "{%0,%1,%2,%3}, {%4,%5,%6,%7}, {%8,%9}, {%0,%1,%2,%3};"
                 : "+f"(c0), "+f"(c1), "+f"(c2), "+f"(c3)
                 : "r"(a0), "r"(a1), "r"(a2), "r"(a3), "r"(b0), "r"(b1));
}
__device__ __forceinline__ void mma16816bf(float* c,
                                           const uint32_t* a,
                                           uint32_t b0, uint32_t b1) {
    asm volatile("mma.sync.aligned.m16n8k16.row.col.f32.bf16.bf16.f32 "
                 "{%0,%1,%2,%3}, {%4,%5,%6,%7}, {%8,%9}, {%0,%1,%2,%3};"
                 : "+f"(c[0]), "+f"(c[1]), "+f"(c[2]), "+f"(c[3])
                 : "r"(a[0]), "r"(a[1]), "r"(a[2]), "r"(a[3]), "r"(b0), "r"(b1));
}
// split float pair into packed bf16 hi and lo words
__device__ __forceinline__ void splitpack(float x, float y, uint32_t& hi, uint32_t& lo) {
    __nv_bfloat16 hx = __float2bfloat16(x), hy = __float2bfloat16(y);
    __nv_bfloat162 h2; h2.x = hx; h2.y = hy;
    hi = *(uint32_t*)&h2;
    __nv_bfloat16 lx = __float2bfloat16(x - __bfloat162float(hx));
    __nv_bfloat16 ly = __float2bfloat16(y - __bfloat162float(hy));
    __nv_bfloat162 l2; l2.x = lx; l2.y = ly;
    lo = *(uint32_t*)&l2;
}

// ---------------------------------------------------------------------------
// K0: continuous position bias MLP + gather + 16*sigmoid
// ---------------------------------------------------------------------------
__global__ void rpb_kernel(const float* __restrict__ table,
                           const float* __restrict__ w1,
                           const float* __restrict__ b1,
                           const float* __restrict__ w2,
                           const float* __restrict__ b2,
                           const int*   __restrict__ idx)
{
    __shared__ float s_w1[1024];
    __shared__ float s_b1[512];
    __shared__ float s_w2[512 * 12];
    __shared__ float s_b2[12];
    __shared__ float s_rpb[225 * 12];
    int tid = threadIdx.x;

    for (int i = tid; i < 1024; i += 256) s_w1[i] = w1[i];
    for (int i = tid; i < 512;  i += 256) s_b1[i] = b1[i];
    for (int i = tid; i < 6144; i += 256) s_w2[i] = w2[i];
    if (tid < 12) s_b2[tid] = b2[tid];
    __syncthreads();

    if (tid < 225) {
        float t0 = table[tid * 2 + 0];
        float t1 = table[tid * 2 + 1];
        float acc[12];
        #pragma unroll
        for (int h = 0; h < 12; h++) acc[h] = s_b2[h];
        for (int j = 0; j < 512; j++) {
            float hj = fmaf(t0, s_w1[j], fmaf(t1, s_w1[512 + j], s_b1[j]));
            hj = fmaxf(hj, 0.0f);
            #pragma unroll
            for (int h = 0; h < 12; h++)
                acc[h] = fmaf(hj, s_w2[j * 12 + h], acc[h]);
        }
        #pragma unroll
        for (int h = 0; h < 12; h++) s_rpb[tid * 12 + h] = acc[h];
    }
    __syncthreads();

    for (int o = tid; o < NHEADS * NT * NT; o += 256) {
        int h = o >> 12;
        int p = o & 4095;
        float r = s_rpb[idx[p] * 12 + h];
        g_bias[o] = 16.0f / (1.0f + expf(-r));
    }
}

// combine bias (per head) + mask (per window group) into one L2-resident table
__global__ __launch_bounds__(256) void bm_kernel(const float* __restrict__ mask)
{
    int hw = blockIdx.x;                 // 0..767 = h*64 + w
    const float* bi = g_bias + (hw >> 6) * 4096;
    const float* mk = mask + (size_t)(hw & 63) * 4096;
    float* o = g_bm + (size_t)hw * 4096;
    for (int i = threadIdx.x; i < 4096; i += 256) o[i] = bi[i] + mk[i];
}

// ---------------------------------------------------------------------------
// Convert fp32 activations -> fp16
// ---------------------------------------------------------------------------
__global__ __launch_bounds__(256) void conv_act(const float* __restrict__ in,
                                                __half* __restrict__ out)
{
    size_t t = (size_t)blockIdx.x * 256 + threadIdx.x;
    if (t >= (size_t)MTOK * 96) return;
    float4 v = *(const float4*)(in + t * 4);
    __half2 p0 = __floats2half2_rn(v.x, v.y);
    __half2 p1 = __floats2half2_rn(v.z, v.w);
    __half2* o = (__half2*)(out + t * 4);
    o[0] = p0; o[1] = p1;
}

// Convert + transpose weights [384 x Ncols] fp32 -> fp16 [Ncols x 384]
__global__ __launch_bounds__(256) void conv_w(const float* __restrict__ w,
                                              __half* __restrict__ out, int Ncols)
{
    int t = blockIdx.x * 256 + threadIdx.x;
    if (t >= DIMF * Ncols) return;
    int k = t / Ncols, n = t % Ncols;
    out[(size_t)n * DIMF + k] = __float2half(w[(size_t)k * Ncols + n]);
}

// ---------------------------------------------------------------------------
// HMMA fp16 GEMM: C = A[M,K] @ B[N,K]^T (+bias).
// Dual-format epilogue: column tiles with n0 >= 768 (the V part of QKV) are
// written fp16 into Ch (stride 384, col - 768); others fp32 into C (ldc).
// ---------------------------------------------------------------------------
__global__ __launch_bounds__(256) void gemm_hmma(
    const __half* __restrict__ A, const __half* __restrict__ B,
    const float* __restrict__ bias, float* __restrict__ C, __half* __restrict__ Ch,
    int ldc, int K)
{
    __shared__ alignas(16) __half sA[2][128 * ASTRIDE];
    __shared__ alignas(16) __half sB[2][128 * ASTRIDE];

    const int tid  = threadIdx.x;
    const int wid  = tid >> 5, lane = tid & 31;
    const int m0   = blockIdx.y * 128, n0 = blockIdx.x * 128;
    const int wm   = (wid & 1) * 64;
    const int wn   = (wid >> 1) * 32;
    const int KT   = K / BK;

    float c[4][4][4];
    #pragma unroll
    for (int i = 0; i < 4; i++)
        #pragma unroll
        for (int j = 0; j < 4; j++)
            #pragma unroll
            for (int l = 0; l < 4; l++) c[i][j][l] = 0.0f;

    const int lrow = tid >> 2;
    const int lq   = tid & 3;
    const __half* gA0 = A + (size_t)(m0 + lrow)      * K + lq * 8;
    const __half* gA1 = A + (size_t)(m0 + lrow + 64) * K + lq * 8;
    const __half* gB0 = B + (size_t)(n0 + lrow)      * K + lq * 8;
    const __half* gB1 = B + (size_t)(n0 + lrow + 64) * K + lq * 8;

    uint32_t sA_st[2], sB_st[2], sA_base[2], sB_base[2];
    #pragma unroll
    for (int s = 0; s < 2; s++) {
        sA_base[s] = smem_u32(&sA[s][0]);
        sB_base[s] = smem_u32(&sB[s][0]);
        sA_st[s] = sA_base[s] + (lrow * ASTRIDE + lq * 8) * 2;
        sB_st[s] = sB_base[s] + (lrow * ASTRIDE + lq * 8) * 2;
    }
    const uint32_t rowoff = 64 * ASTRIDE * 2;

    const uint32_t a_off = ((wm + (lane & 15)) * ASTRIDE + (lane >> 4) * 8) * 2;
    const uint32_t b_off = ((wn + (lane & 7) + ((lane >> 4) << 3)) * ASTRIDE
                            + ((lane >> 3) & 1) * 8) * 2;

    {
        cp_async16(sA_st[0],          gA0);
        cp_async16(sA_st[0] + rowoff, gA1);
        cp_async16(sB_st[0],          gB0);
        cp_async16(sB_st[0] + rowoff, gB1);
        asm volatile("cp.async.commit_group;" ::: "memory");
    }

    for (int kt = 0; kt < KT; kt++) {
        const int cur = kt & 1;
        if (kt + 1 < KT) {
            const int nxt = cur ^ 1;
            const size_t ko = (size_t)(kt + 1) * BK;
            cp_async16(sA_st[nxt],          gA0 + ko);
            cp_async16(sA_st[nxt] + rowoff, gA1 + ko);
            cp_async16(sB_st[nxt],          gB0 + ko);
            cp_async16(sB_st[nxt] + rowoff, gB1 + ko);
            asm volatile("cp.async.commit_group;" ::: "memory");
            asm volatile("cp.async.wait_group 1;" ::: "memory");
        } else {
            asm volatile("cp.async.wait_group 0;" ::: "memory");
        }
        __syncthreads();

        const uint32_t aS = sA_base[cur] + a_off;
        const uint32_t bS = sB_base[cur] + b_off;
        #pragma unroll
        for (int kk = 0; kk < 2; kk++) {
            uint32_t a[4][4];
            #pragma unroll
            for (int mi = 0; mi < 4; mi++)
                ldm_x4(a[mi][0], a[mi][1], a[mi][2], a[mi][3],
                       aS + (mi * 16 * ASTRIDE + kk * 16) * 2);
            uint32_t b[4][2];
            #pragma unroll
            for (int p = 0; p < 2; p++) {
                uint32_t r0, r1, r2, r3;
                ldm_x4(r0, r1, r2, r3, bS + (p * 16 * ASTRIDE + kk * 16) * 2);
                b[p * 2 + 0][0] = r0; b[p * 2 + 0][1] = r1;
                b[p * 2 + 1][0] = r2; b[p * 2 + 1][1] = r3;
            }
            #pragma unroll
            for (int mi = 0; mi < 4; mi++)
                #pragma unroll
                for (int ni = 0; ni < 4; ni++)
                    mma16816(c[mi][ni][0], c[mi][ni][1], c[mi][ni][2], c[mi][ni][3],
                             a[mi][0], a[mi][1], a[mi][2], a[mi][3],
                             b[ni][0], b[ni][1]);
        }
        __syncthreads();
    }

    const int g = lane >> 2, tg = lane & 3;
    const bool halfout = (Ch != nullptr) && (n0 >= 768);
    if (halfout) {
        // V tiles -> fp16, stride DIMF, columns rebased to 0
        #pragma unroll
        for (int ni = 0; ni < 4; ni++) {
            const int col = (n0 - 768) + wn + ni * 8 + tg * 2;
            #pragma unroll
            for (int mi = 0; mi < 4; mi++) {
                const int row = m0 + wm + mi * 16 + g;
                *(__half2*)(Ch + (size_t)row * DIMF + col) =
                    __floats2half2_rn(c[mi][ni][0], c[mi][ni][1]);
                *(__half2*)(Ch + (size_t)(row + 8) * DIMF + col) =
                    __floats2half2_rn(c[mi][ni][2], c[mi][ni][3]);
            }
        }
    } else {
        #pragma unroll
        for (int ni = 0; ni < 4; ni++) {
            const int col = n0 + wn + ni * 8 + tg * 2;
            float b0 = 0.0f, b1 = 0.0f;
            if (bias) { b0 = bias[col]; b1 = bias[col + 1]; }
            #pragma unroll
            for (int mi = 0; mi < 4; mi++) {
                const int row = m0 + wm + mi * 16 + g;
                float2 v0 = make_float2(c[mi][ni][0] + b0, c[mi][ni][1] + b1);
                float2 v1 = make_float2(c[mi][ni][2] + b0, c[mi][ni][3] + b1);
                *(float2*)(C + (size_t)row * ldc + col)       = v0;
                *(float2*)(C + (size_t)(row + 8) * ldc + col) = v1;
            }
        }
    }
}

// ---------------------------------------------------------------------------
// K2: attention via split-2 bf16 tensor-core MMA. One CTA per (head, window).
// q,k fp32 (stride 768); v fp16 (stride 384). PV B-operand via ldmatrix.trans.
// ---------------------------------------------------------------------------
__global__ __launch_bounds__(128) void attn_kernel(const float* __restrict__ lscale)
{
    const int h   = blockIdx.x;
    const int b   = blockIdx.y;
    const int tid = threadIdx.x;
    const int wid = tid >> 5, lane = tid & 31;
    const int g   = lane >> 2, tg = lane & 3;
    const int wm  = wid * 16;

    __shared__ alignas(16) __nv_bfloat16 sqh[64 * ASTRIDE], sql[64 * ASTRIDE];
    __shared__ alignas(16) __nv_bfloat16 skh[64 * ASTRIDE], skl[64 * ASTRIDE];
    __shared__ alignas(16) __nv_bfloat16 svh[64 * ASTRIDE], svl[64 * ASTRIDE]; // [key][d]

    // ---- load + normalize q (threads 0-63) / k (threads 64-127), split bf16
    {
        int r = tid & 63;
        const float4* p = (const float4*)(g_qkv + (size_t)(b * 64 + r) * QKCOLS
                                          + h * 32 + (tid < 64 ? 0 : 384));
        float v[32];
        #pragma unroll
        for (int i = 0; i < 8; i++) {
            float4 t = p[i];
            v[i * 4 + 0] = t.x; v[i * 4 + 1] = t.y; v[i * 4 + 2] = t.z; v[i * 4 + 3] = t.w;
        }
        float ss = 0.0f;
        #pragma unroll
        for (int i = 0; i < 32; i++) ss = fmaf(v[i], v[i], ss);
        float sc = rsqrtf(fmaxf(ss, 1e-12f));
        if (tid < 64) sc *= __expf(fminf(lscale[h], MAX_LOGIT));
        uint32_t* rh = (uint32_t*)((tid < 64 ? sqh : skh) + r * ASTRIDE);
        uint32_t* rl = (uint32_t*)((tid < 64 ? sql : skl) + r * ASTRIDE);
        #pragma unroll
        for (int i = 0; i < 16; i++) {
            uint32_t hi, lo;
            splitpack(v[2 * i] * sc, v[2 * i + 1] * sc, hi, lo);
            rh[i] = hi; rl[i] = lo;
        }
    }
    // ---- load v fp16 (all threads), split bf16, natural [key][d] layout
    {
        int r = tid >> 1, dh = (tid & 1) * 16;
        const uint4* p = (const uint4*)(g_v + (size_t)(b * 64 + r) * DIMF + h * 32 + dh);
        uint4 u0 = p[0], u1 = p[1];   // 16 halves
        uint32_t uu[4] = {u0.x, u0.y, u0.z, u0.w};
        uint32_t vv[4] = {u1.x, u1.y, u1.z, u1.w};
        uint32_t wh[8], wl[8];
        #pragma unroll
        for (int i = 0; i < 4; i++) {
            float2 f0 = __half22float2(*(__half2*)&uu[i]);
            splitpack(f0.x, f0.y, wh[i], wl[i]);
            float2 f1 = __half22float2(*(__half2*)&vv[i]);
            splitpack(f1.x, f1.y, wh[4 + i], wl[4 + i]);
        }
        uint4* oh = (uint4*)(svh + r * ASTRIDE + dh);
        uint4* ol = (uint4*)(svl + r * ASTRIDE + dh);
        oh[0] = make_uint4(wh[0], wh[1], wh[2], wh[3]);
        oh[1] = make_uint4(wh[4], wh[5], wh[6], wh[7]);
        ol[0] = make_uint4(wl[0], wl[1], wl[2], wl[3]);
        ol[1] = make_uint4(wl[4], wl[5], wl[6], wl[7]);
    }
    __syncthreads();

    // ---- scores: c[8 key-frags][4], split-2 bf16 MMA
    float c[8][4];
    #pragma unroll
    for (int j = 0; j < 8; j++)
        #pragma unroll
        for (int l = 0; l < 4; l++) c[j][l] = 0.0f;

    const uint32_t a_off = ((wm + (lane & 15)) * ASTRIDE + (lane >> 4) * 8) * 2;
    const uint32_t b_off = (((lane & 7) + ((lane >> 4) << 3)) * ASTRIDE
                            + ((lane >> 3) & 1) * 8) * 2;

    uint32_t ah[2][4], al[2][4];
    ldm_x4(ah[0][0], ah[0][1], ah[0][2], ah[0][3], smem_u32(sqh) + a_off);
    ldm_x4(ah[1][0], ah[1][1], ah[1][2], ah[1][3], smem_u32(sqh) + a_off + 32);
    ldm_x4(al[0][0], al[0][1], al[0][2], al[0][3], smem_u32(sql) + a_off);
    ldm_x4(al[1][0], al[1][1], al[1][2], al[1][3], smem_u32(sql) + a_off + 32);

    #pragma unroll
    for (int kb = 0; kb < 4; kb++) {
        uint32_t bh[2][2][2], bl[2][2][2];   // [kk][nfrag][2]
        #pragma unroll
        for (int kk = 0; kk < 2; kk++) {
            uint32_t r0, r1, r2, r3;
            ldm_x4(r0, r1, r2, r3,
                   smem_u32(skh) + b_off + kb * (16 * ASTRIDE * 2) + kk * 32);
            bh[kk][0][0] = r0; bh[kk][0][1] = r1; bh[kk][1][0] = r2; bh[kk][1][1] = r3;
            ldm_x4(r0, r1, r2, r3,
                   smem_u32(skl) + b_off + kb * (16 * ASTRIDE * 2) + kk * 32);
            bl[kk][0][0] = r0; bl[kk][0][1] = r1; bl[kk][1][0] = r2; bl[kk][1][1] = r3;
        }
        #pragma unroll
        for (int nf = 0; nf < 2; nf++) {
            int n = kb * 2 + nf;
            #pragma unroll
            for (int kk = 0; kk < 2; kk++) {
                mma16816bf(c[n], ah[kk], bh[kk][nf][0], bh[kk][nf][1]);  // hi*hi
                mma16816bf(c[n], ah[kk], bl[kk][nf][0], bl[kk][nf][1]);  // hi*lo
                mma16816bf(c[n], al[kk], bh[kk][nf][0], bh[kk][nf][1]);  // lo*hi
            }
        }
    }

    // ---- add combined bias+mask (single L2-resident table)
    {
        const float* bm = g_bm + ((size_t)h * 64 + (b & 63)) * 4096;
        #pragma unroll
        for (int j = 0; j < 8; j++) {
            int cb = j * 8 + tg * 2;
            float2 m0 = *(const float2*)(bm + (wm + g) * 64 + cb);
            float2 m1 = *(const float2*)(bm + (wm + g + 8) * 64 + cb);
            c[j][0] += m0.x; c[j][1] += m0.y; c[j][2] += m1.x; c[j][3] += m1.y;
        }
    }

    // ---- fragment softmax (rows wm+g and wm+g+8)
    {
        float m0 = -1e30f, m1 = -1e30f;
        #pragma unroll
        for (int j = 0; j < 8; j++) {
            m0 = fmaxf(m0, fmaxf(c[j][0], c[j][1]));
            m1 = fmaxf(m1, fmaxf(c[j][2], c[j][3]));
        }
        m0 = fmaxf(m0, __shfl_xor_sync(0xFFFFFFFF, m0, 1));
        m0 = fmaxf(m0, __shfl_xor_sync(0xFFFFFFFF, m0, 2));
        m1 = fmaxf(m1, __shfl_xor_sync(0xFFFFFFFF, m1, 1));
        m1 = fmaxf(m1, __shfl_xor_sync(0xFFFFFFFF, m1, 2));
        float s0 = 0.0f, s1 = 0.0f;
        #pragma unroll
        for (int j = 0; j < 8; j++) {
            c[j][0] = __expf(c[j][0] - m0); s0 += c[j][0];
            c[j][1] = __expf(c[j][1] - m0); s0 += c[j][1];
            c[j][2] = __expf(c[j][2] - m1); s1 += c[j][2];
            c[j][3] = __expf(c[j][3] - m1); s1 += c[j][3];
        }
        s0 += __shfl_xor_sync(0xFFFFFFFF, s0, 1);
        s0 += __shfl_xor_sync(0xFFFFFFFF, s0, 2);
        s1 += __shfl_xor_sync(0xFFFFFFFF, s1, 1);
        s1 += __shfl_xor_sync(0xFFFFFFFF, s1, 2);
        float i0 = 1.0f / s0, i1 = 1.0f / s1;
        #pragma unroll
        for (int j = 0; j < 8; j++) {
            c[j][0] *= i0; c[j][1] *= i0; c[j][2] *= i1; c[j][3] *= i1;
        }
    }

    // ---- pack P fragments (A-layout) with split-2
    uint32_t ph[4][4], pl[4][4];   // [kstep][4 regs]
    #pragma unroll
    for (int ks = 0; ks < 4; ks++) {
        int j0 = 2 * ks, j1 = 2 * ks + 1;
        splitpack(c[j0][0], c[j0][1], ph[ks][0], pl[ks][0]);
        splitpack(c[j0][2], c[j0][3], ph[ks][1], pl[ks][1]);
        splitpack(c[j1][0], c[j1][1], ph[ks][2], pl[ks][2]);
        splitpack(c[j1][2], c[j1][3], ph[ks][3], pl[ks][3]);
    }

    // ---- PV: o[4 d-frags][4]; B via trans-ldmatrix of natural-layout V
    float o[4][4];
    #pragma unroll
    for (int n = 0; n < 4; n++)
        #pragma unroll
        for (int l = 0; l < 4; l++) o[n][l] = 0.0f;

    const uint32_t vt_off = (((lane & 7) + ((lane >> 3) & 1) * 8) * ASTRIDE
                             + (lane >> 4) * 8) * 2;
    #pragma unroll
    for (int ng = 0; ng < 2; ng++) {          // d 16-col group
        #pragma unroll
        for (int ks = 0; ks < 4; ks++) {      // key 16-row block
            uint32_t r0, r1, r2, r3, s0, s1, s2, s3;
            ldm_x4_trans(r0, r1, r2, r3,
                         smem_u32(svh) + vt_off + ks * (16 * ASTRIDE * 2) + ng * 32);
            ldm_x4_trans(s0, s1, s2, s3,
                         smem_u32(svl) + vt_off + ks * (16 * ASTRIDE * 2) + ng * 32);
            int n0i = ng * 2, n1i = ng * 2 + 1;
            mma16816bf(o[n0i], ph[ks], r0, r1);   // ph*vh
            mma16816bf(o[n0i], ph[ks], s0, s1);   // ph*vl
            mma16816bf(o[n0i], pl[ks], r0, r1);   // pl*vh
            mma16816bf(o[n1i], ph[ks], r2, r3);
            mma16816bf(o[n1i], ph[ks], s2, s3);
            mma16816bf(o[n1i], pl[ks], r2, r3);
        }
    }

    // ---- write fp16 ctx to g_a
    {
        __half* o0 = g_a + (size_t)(b * 64 + wm + g) * DIMF + h * 32;
        __half* o1 = o0 + (size_t)8 * DIMF;
        #pragma unroll
        for (int n = 0; n < 4; n++) {
            int col = n * 8 + tg * 2;
            *(__half2*)(o0 + col) = __floats2half2_rn(o[n][0], o[n][1]);
            *(__half2*)(o1 + col) = __floats2half2_rn(o[n][2], o[n][3]);
        }
    }
}

// ---------------------------------------------------------------------------
extern "C" void kernel_launch(void* const* d_in, const int* in_sizes, int n_in,
                              void* d_out, int out_size)
{
    const float* x           = (const float*)d_in[0];
    const float* mask        = (const float*)d_in[1];
    const float* qkv_w       = (const float*)d_in[2];
    const float* proj_w      = (const float*)d_in[3];
    const float* proj_b      = (const float*)d_in[4];
    const float* cpb_w1      = (const float*)d_in[5];
    const float* cpb_b1      = (const float*)d_in[6];
    const float* cpb_w2      = (const float*)d_in[7];
    const float* cpb_b2      = (const float*)d_in[8];
    const float* logit_scale = (const float*)d_in[9];
    const float* rpb_table   = (const float*)d_in[10];
    const int*   rpb_idx     = (const int*)d_in[11];
    float* out = (float*)d_out;

    float* qkv_ptr = nullptr;
    __half *a_ptr = nullptr, *v_ptr = nullptr, *wq_ptr = nullptr, *wp_ptr = nullptr;
    cudaGetSymbolAddress((void**)&qkv_ptr, g_qkv);
    cudaGetSymbolAddress((void**)&a_ptr,  g_a);
    cudaGetSymbolAddress((void**)&v_ptr,  g_v);
    cudaGetSymbolAddress((void**)&wq_ptr, g_wq);
    cudaGetSymbolAddress((void**)&wp_ptr, g_wp);

    // K0: CPB bias table + bias/mask combine + weight converts (tiny)
    rpb_kernel<<<1, 256>>>(rpb_table, cpb_w1, cpb_b1, cpb_w2, cpb_b2, rpb_idx);
    bm_kernel<<<NHEADS * 64, 256>>>(mask);
    conv_w<<<(DIMF * QKVCOLS + 255) / 256, 256>>>(qkv_w, wq_ptr, QKVCOLS);
    conv_w<<<(DIMF * DIMF + 255) / 256, 256>>>(proj_w, wp_ptr, DIMF);

    // convert activations for QKV GEMM
    conv_act<<<(int)(((size_t)MTOK * 96 + 255) / 256), 256>>>(x, a_ptr);

    // K1: QKV GEMM (65536 x 1152 x 384); q,k -> fp32 (stride 768), v -> fp16
    gemm_hmma<<<dim3(QKVCOLS / 128, MTOK / 128), 256>>>(
        a_ptr, wq_ptr, nullptr, qkv_ptr, v_ptr, QKCOLS, DIMF);

    // K2: attention per (head, window); tensor-core split-bf16; writes fp16 ctx
    attn_kernel<<<dim3(NHEADS, NWIN), 128>>>(logit_scale);

    // K3: projection (65536 x 384 x 384) + bias, fp16 HMMA
    gemm_hmma<<<dim3(DIMF / 128, MTOK / 128), 256>>>(
        a_ptr, wp_ptr, proj_b, out, nullptr, DIMF, DIMF);
}